// round 15
// baseline (speedup 1.0000x reference)
#include <cuda_runtime.h>
#include <cuda_bf16.h>
#include <math.h>
#include <stdint.h>

#define KS 14      // source subjects (S-1)
#define SNUM 15
#define BSZ 1024
#define CD 2048
#define DD 512
#define M2 2048

#define STAGE_B 32768u      // mm1 stage bytes
#define SMEM_FUSED (3 * 32768)
#define GSTAGE_B 32768u     // gram stage bytes (K-chunk 64)

#define SPLIT_SLICES 64
// interleaved prologue: [split p0][split p1][mm1 k0][split p2][mm1 k1]...
#define B_INTER (64 + 14 * 128)             // 1856 = 960 split + 896 mm1
#define GRAM_PER_K 136                      // 16*17/2 upper-triangle tiles
#define GRAM_CTAS (KS * GRAM_PER_K)         // 1904
#define CLS_CTAS BSZ                        // 1024
#define B_CLS   (B_INTER + GRAM_CTAS)       // 3760
#define B_FIN   (B_CLS + CLS_CTAS)          // 4784
#define TOT_CTAS (B_FIN + 1)                // 4785

// ---------------- scratch (static zero-init; fin resets per run) -------------
__device__ __nv_bfloat16 g_x1[(size_t)SNUM * BSZ * CD];
__device__ __nv_bfloat16 g_x2[(size_t)SNUM * BSZ * CD];
__device__ __nv_bfloat16 g_w1[(size_t)SNUM * DD * CD];
__device__ __nv_bfloat16 g_w2[(size_t)SNUM * DD * CD];
__device__ __nv_bfloat16 g_t1[(size_t)KS * M2 * DD];
__device__ float  g_total[(size_t)KS * M2 * DD];
__device__ float  g_sq[KS * M2];
__device__ float  g_cs[KS * DD];
__device__ float  g_inv16[KS];
__device__ int    g_bwflag[KS];
__device__ int    g_sdone[SNUM];
__device__ int    g_done[KS];
__device__ int    g_mm1all;
__device__ int    g_gdone;
__device__ int    g_cdone;
__device__ double g_mmd[KS];
__device__ double g_cls;
__device__ double g_disc;
__device__ int    g_pred;

// ---------------- helpers (compute_80-level PTX only) ----------------
__device__ __forceinline__ uint32_t smem_u32(const void* p) {
    uint32_t a;
    asm("{ .reg .u64 t; cvta.to.shared.u64 t, %1; cvt.u32.u64 %0, t; }" : "=r"(a) : "l"(p));
    return a;
}
__device__ __forceinline__ void cpa(uint32_t dst, const void* src) {
    asm volatile("cp.async.cg.shared.global [%0], [%1], 16;" :: "r"(dst), "l"(src) : "memory");
}
__device__ __forceinline__ void ldsm4(uint32_t* r, uint32_t a) {
    asm volatile("ldmatrix.sync.aligned.m8n8.x4.shared.b16 {%0,%1,%2,%3}, [%4];"
                 : "=r"(r[0]), "=r"(r[1]), "=r"(r[2]), "=r"(r[3]) : "r"(a));
}
__device__ __forceinline__ void mma16816(float* c, const uint32_t* a, const uint32_t* b) {
    asm volatile("mma.sync.aligned.m16n8k16.row.col.f32.bf16.bf16.f32 "
                 "{%0,%1,%2,%3}, {%4,%5,%6,%7}, {%8,%9}, {%0,%1,%2,%3};"
                 : "+f"(c[0]), "+f"(c[1]), "+f"(c[2]), "+f"(c[3])
                 : "r"(a[0]), "r"(a[1]), "r"(a[2]), "r"(a[3]), "r"(b[0]), "r"(b[1]));
}
__device__ __forceinline__ int ld_acq(const int* p) {
    int v;
    asm volatile("ld.acquire.gpu.b32 %0, [%1];" : "=r"(v) : "l"(p) : "memory");
    return v;
}
__device__ __forceinline__ void spin_eq(const int* p, int want) {
    if (threadIdx.x == 0) {
        while (ld_acq(p) != want) __nanosleep(64);
    }
    __syncthreads();
}

// ================= split item: 1/64 of one subject's x+W bf16 hi/lo ==========
__device__ void split_item(int p, int slice, int subj, const float* __restrict__ x,
                           const float* __restrict__ W) {
    int s = (p == 0) ? subj : (((p - 1) < subj) ? (p - 1) : p);
    const int XC = BSZ * CD / 4 / SPLIT_SLICES;   // 8192 float4
    const int WC = DD * CD / 4 / SPLIT_SLICES;    // 4096 float4
    size_t xo = (size_t)s * (BSZ * CD / 4) + (size_t)slice * XC;
    #pragma unroll 8
    for (int i = 0; i < XC / 256; i++) {
        size_t u = xo + i * 256 + threadIdx.x;
        float4 v = ((const float4*)x)[u];
        __nv_bfloat162 h0, h1, l0, l1;
        h0.x = __float2bfloat16(v.x); h0.y = __float2bfloat16(v.y);
        h1.x = __float2bfloat16(v.z); h1.y = __float2bfloat16(v.w);
        l0.x = __float2bfloat16(v.x - __bfloat162float(h0.x));
        l0.y = __float2bfloat16(v.y - __bfloat162float(h0.y));
        l1.x = __float2bfloat16(v.z - __bfloat162float(h1.x));
        l1.y = __float2bfloat16(v.w - __bfloat162float(h1.y));
        ((__nv_bfloat162*)g_x1)[2 * u] = h0; ((__nv_bfloat162*)g_x1)[2 * u + 1] = h1;
        ((__nv_bfloat162*)g_x2)[2 * u] = l0; ((__nv_bfloat162*)g_x2)[2 * u + 1] = l1;
    }
    size_t wo = (size_t)s * (DD * CD / 4) + (size_t)slice * WC;
    #pragma unroll 8
    for (int i = 0; i < WC / 256; i++) {
        size_t u = wo + i * 256 + threadIdx.x;
        float4 v = ((const float4*)W)[u];
        __nv_bfloat162 h0, h1, l0, l1;
        h0.x = __float2bfloat16(v.x); h0.y = __float2bfloat16(v.y);
        h1.x = __float2bfloat16(v.z); h1.y = __float2bfloat16(v.w);
        l0.x = __float2bfloat16(v.x - __bfloat162float(h0.x));
        l0.y = __float2bfloat16(v.y - __bfloat162float(h0.y));
        l1.x = __float2bfloat16(v.z - __bfloat162float(h1.x));
        l1.y = __float2bfloat16(v.w - __bfloat162float(h1.y));
        ((__nv_bfloat162*)g_w1)[2 * u] = h0; ((__nv_bfloat162*)g_w1)[2 * u + 1] = h1;
        ((__nv_bfloat162*)g_w2)[2 * u] = l0; ((__nv_bfloat162*)g_w2)[2 * u + 1] = l1;
    }
    __threadfence();
    __syncthreads();
    if (threadIdx.x == 0) atomicAdd(&g_sdone[s], 1);
}

// ================= mm1 path: 8 warps, warp tile 64x32, 3-product ============
__device__ __forceinline__ void ld_stage(uint32_t sb, int stg,
        const __nv_bfloat16* A1, const __nv_bfloat16* A2,
        const __nv_bfloat16* B1, const __nv_bfloat16* B2, int kt) {
    int tid = threadIdx.x;
    int half = tid & 1, row = tid >> 1;
    uint32_t s0 = sb + (uint32_t)stg * STAGE_B;
    uint32_t roff = (uint32_t)(row * 32) + (uint32_t)((half ^ ((row >> 2) & 1)) * 16);
    const __nv_bfloat16* ptrs[4] = {A1, A2, B1, B2};
    #pragma unroll
    for (int it = 0; it < 8; it++) {
        const int arr = it >> 1, kc = it & 1;
        cpa(s0 + (uint32_t)(arr * 8192 + kc * 4096) + roff,
            ptrs[arr] + (size_t)row * CD + kt + kc * 16 + half * 8);
    }
    asm volatile("cp.async.commit_group;" ::: "memory");
}

__device__ __forceinline__ void cmp_stage(uint32_t s0, int wm, int wn, int lane,
                                          float (*acc)[4][4]) {
    int arow = wm * 64 + (lane & 15);
    int ah = lane >> 4;
    int brow = wn * 32 + (lane & 7) + ((lane >> 4) << 3);
    int bh = (lane >> 3) & 1;
    #pragma unroll
    for (int kk = 0; kk < 2; kk++) {
        uint32_t base = s0 + (uint32_t)(kk * 4096);
        uint32_t af1[4][4], af2[4][4], bfr1[2][4], bfr2[2][4];
        #pragma unroll
        for (int mf = 0; mf < 4; mf++) {
            int r = arow + mf * 16;
            uint32_t off = (uint32_t)(r * 32 + ((ah ^ ((r >> 2) & 1)) * 16));
            ldsm4(af1[mf], base + off);
            ldsm4(af2[mf], base + 8192 + off);
        }
        #pragma unroll
        for (int np = 0; np < 2; np++) {
            int r = brow + np * 16;
            uint32_t off = (uint32_t)(r * 32 + ((bh ^ ((r >> 2) & 1)) * 16));
            ldsm4(bfr1[np], base + 16384 + off);
            ldsm4(bfr2[np], base + 24576 + off);
        }
        #pragma unroll
        for (int mf = 0; mf < 4; mf++)
            #pragma unroll
            for (int nf = 0; nf < 4; nf++) {
                const uint32_t* b1 = &bfr1[nf >> 1][(nf & 1) * 2];
                const uint32_t* b2 = &bfr2[nf >> 1][(nf & 1) * 2];
                mma16816(acc[mf][nf], af1[mf], b1);
                mma16816(acc[mf][nf], af1[mf], b2);
                mma16816(acc[mf][nf], af2[mf], b1);
            }
    }
}

__device__ void mm1_work(uint32_t sb, int k, int t,
                         const float* __restrict__ b_add, int subj) {
    int n0 = (t & 3) * 128;
    int i0 = (t >> 2) * 128;
    int sk = (k < subj) ? k : k + 1;

    // wait for bf16 splits of the two subjects this tile reads
    if (threadIdx.x == 0) {
        while (ld_acq(&g_sdone[sk]) != SPLIT_SLICES) __nanosleep(64);
        while (ld_acq(&g_sdone[subj]) != SPLIT_SLICES) __nanosleep(64);
    }
    __syncthreads();

    int arow0 = (i0 < BSZ) ? (sk * BSZ + i0) : (subj * BSZ + (i0 - BSZ));
    const __nv_bfloat16* A1 = g_x1 + (size_t)arow0 * CD;
    const __nv_bfloat16* A2 = g_x2 + (size_t)arow0 * CD;
    const __nv_bfloat16* B1 = g_w1 + ((size_t)sk * DD + n0) * CD;
    const __nv_bfloat16* B2 = g_w2 + ((size_t)sk * DD + n0) * CD;

    float acc[4][4][4];
    #pragma unroll
    for (int a = 0; a < 4; a++)
        #pragma unroll
        for (int b = 0; b < 4; b++)
            #pragma unroll
            for (int c = 0; c < 4; c++) acc[a][b][c] = 0.f;

    int tid = threadIdx.x, lane = tid & 31, wid = tid >> 5;
    int wm = wid & 1, wn = wid >> 1;
    ld_stage(sb, 0, A1, A2, B1, B2, 0);
    ld_stage(sb, 1, A1, A2, B1, B2, 32);
    const int NT = CD / 32;
    for (int ic = 0; ic < NT; ic++) {
        asm volatile("cp.async.wait_group 1;" ::: "memory");
        __syncthreads();
        if (ic + 2 < NT)
            ld_stage(sb, (ic + 2) % 3, A1, A2, B1, B2, (ic + 2) * 32);
        else
            asm volatile("cp.async.commit_group;" ::: "memory");
        cmp_stage(sb + (uint32_t)(ic % 3) * STAGE_B, wm, wn, lane, acc);
    }
    __syncthreads();

    // epilogue: bias, store fp32 + bf16(hi), row sq-norms, fused column sums
    int rb = i0 + wm * 64 + (lane >> 2);
    int cb = n0 + wn * 32 + 2 * (lane & 3);
    float csum[8];
    #pragma unroll
    for (int q = 0; q < 8; q++) csum[q] = 0.f;
    #pragma unroll
    for (int mf = 0; mf < 4; mf++) {
        #pragma unroll
        for (int rr = 0; rr < 2; rr++) {
            int row = rb + mf * 16 + rr * 8;
            float* trow = g_total + ((size_t)k * M2 + row) * DD;
            __nv_bfloat16* t1r = g_t1 + ((size_t)k * M2 + row) * DD;
            float s = 0.f;
            #pragma unroll
            for (int nf = 0; nf < 4; nf++) {
                int col = cb + nf * 8;
                float v0 = acc[mf][nf][rr * 2 + 0] + b_add[sk * DD + col];
                float v1 = acc[mf][nf][rr * 2 + 1] + b_add[sk * DD + col + 1];
                *(float2*)(trow + col) = make_float2(v0, v1);
                __nv_bfloat162 ph;
                ph.x = __float2bfloat16(v0);
                ph.y = __float2bfloat16(v1);
                *(__nv_bfloat162*)(t1r + col) = ph;
                s += v0 * v0 + v1 * v1;
                csum[nf * 2 + 0] += v0;
                csum[nf * 2 + 1] += v1;
            }
            s += __shfl_xor_sync(0xffffffffu, s, 1);
            s += __shfl_xor_sync(0xffffffffu, s, 2);
            if ((lane & 3) == 0) atomicAdd(&g_sq[k * M2 + row], s);
        }
    }
    #pragma unroll
    for (int q = 0; q < 8; q++) {
        csum[q] += __shfl_xor_sync(0xffffffffu, csum[q], 4);
        csum[q] += __shfl_xor_sync(0xffffffffu, csum[q], 8);
        csum[q] += __shfl_xor_sync(0xffffffffu, csum[q], 16);
    }
    if ((lane >> 2) == 0) {
        #pragma unroll
        for (int nf = 0; nf < 4; nf++) {
            atomicAdd(&g_cs[k * DD + cb + nf * 8 + 0], csum[nf * 2 + 0]);
            atomicAdd(&g_cs[k * DD + cb + nf * 8 + 1], csum[nf * 2 + 1]);
        }
    }
    __threadfence();
    __syncthreads();
    if (threadIdx.x == 0) {
        atomicAdd(&g_done[k], 1);
        atomicAdd(&g_mm1all, 1);
    }
}

// ================= gram path: 1-product bf16, K-chunk 64, 64x32 warp tile =====
__device__ __forceinline__ void ld_stage_g(uint32_t sb, int stg,
        const __nv_bfloat16* A, const __nv_bfloat16* B, int kt) {
    int tid = threadIdx.x;
    uint32_t s0 = sb + (uint32_t)stg * GSTAGE_B;
    const __nv_bfloat16* ptrs[2] = {A, B};
    #pragma unroll
    for (int it = 0; it < 8; it++) {
        const int arr = it >> 2;
        int u = (it & 3) * 256 + tid;       // 0..1023 within array
        int row = u >> 3;
        int h = u & 7;                       // 16B index within 128B row
        int kc = h >> 1, half = h & 1;
        uint32_t off = (uint32_t)(kc * 4096 + row * 32 + ((half ^ ((row >> 2) & 1)) * 16));
        cpa(s0 + (uint32_t)(arr * 16384) + off,
            ptrs[arr] + (size_t)row * DD + kt + kc * 16 + half * 8);
    }
    asm volatile("cp.async.commit_group;" ::: "memory");
}

__device__ __forceinline__ void cmp_stage_g(uint32_t s0, int wm, int wn, int lane,
                                            float (*acc)[4][4]) {
    int arow = wm * 64 + (lane & 15);
    int ah = lane >> 4;
    int brow = wn * 32 + (lane & 7) + ((lane >> 4) << 3);
    int bh = (lane >> 3) & 1;
    #pragma unroll
    for (int kk = 0; kk < 4; kk++) {
        uint32_t base = s0 + (uint32_t)(kk * 4096);
        uint32_t af[4][4], bfr[2][4];
        #pragma unroll
        for (int mf = 0; mf < 4; mf++) {
            int r = arow + mf * 16;
            uint32_t off = (uint32_t)(r * 32 + ((ah ^ ((r >> 2) & 1)) * 16));
            ldsm4(af[mf], base + off);
        }
        #pragma unroll
        for (int np = 0; np < 2; np++) {
            int r = brow + np * 16;
            uint32_t off = (uint32_t)(r * 32 + ((bh ^ ((r >> 2) & 1)) * 16));
            ldsm4(bfr[np], base + 16384 + off);
        }
        #pragma unroll
        for (int mf = 0; mf < 4; mf++)
            #pragma unroll
            for (int nf = 0; nf < 4; nf++)
                mma16816(acc[mf][nf], af[mf], &bfr[nf >> 1][(nf & 1) * 2]);
    }
}

__device__ void gram_work(uint32_t sb, int gid, char* smem) {
    int k = gid / GRAM_PER_K;
    int t = gid % GRAM_PER_K;
    int bi = 0;
    while (t >= 16 - bi) { t -= 16 - bi; bi++; }
    int bj = bi + t;
    bool bw_owner = (gid % GRAM_PER_K) == 0;

    spin_eq(&g_done[k], 64);

    int tid = threadIdx.x, lane = tid & 31, wid = tid >> 5;
    float* red = (float*)smem;

    // first gram CTA of this k computes 1/(16*bandwidth) for everyone
    if (bw_owner) {
        float s2 = 0.f;
        for (int d = tid; d < DD; d += 256) { float c = g_cs[k * DD + d]; s2 += c * c; }
        float qq = 0.f;
        for (int i = tid; i < M2; i += 256) qq += g_sq[k * M2 + i];
        #pragma unroll
        for (int o = 16; o; o >>= 1) {
            s2 += __shfl_xor_sync(0xffffffffu, s2, o);
            qq += __shfl_xor_sync(0xffffffffu, qq, o);
        }
        if (lane == 0) { red[wid] = s2; red[8 + wid] = qq; }
        __syncthreads();
        if (tid == 0) {
            float ssum = 0.f, sqsum = 0.f;
            #pragma unroll
            for (int i = 0; i < 8; i++) { ssum += red[i]; sqsum += red[8 + i]; }
            double m = (double)M2;
            double sumd2 = 2.0 * m * (double)sqsum - 2.0 * (double)ssum;
            double bw = sumd2 / (m * m - m) / 4.0;
            g_inv16[k] = (float)(1.0 / (16.0 * bw));
            __threadfence();
            atomicExch(&g_bwflag[k], 1);
        }
        __syncthreads();
    }

    int i0 = bi * 128, j0 = bj * 128;
    const __nv_bfloat16* A = g_t1 + ((size_t)k * M2 + i0) * DD;
    const __nv_bfloat16* B = g_t1 + ((size_t)k * M2 + j0) * DD;

    float acc[4][4][4];
    #pragma unroll
    for (int a = 0; a < 4; a++)
        #pragma unroll
        for (int b = 0; b < 4; b++)
            #pragma unroll
            for (int c = 0; c < 4; c++) acc[a][b][c] = 0.f;

    int wm = wid & 1, wn = wid >> 1;
    ld_stage_g(sb, 0, A, B, 0);
    ld_stage_g(sb, 1, A, B, 64);
    const int NT = DD / 64;   // 8 chunks
    for (int ic = 0; ic < NT; ic++) {
        asm volatile("cp.async.wait_group 1;" ::: "memory");
        __syncthreads();
        if (ic + 2 < NT)
            ld_stage_g(sb, (ic + 2) % 3, A, B, (ic + 2) * 64);
        else
            asm volatile("cp.async.commit_group;" ::: "memory");
        cmp_stage_g(sb + (uint32_t)(ic % 3) * GSTAGE_B, wm, wn, lane, acc);
    }
    __syncthreads();

    // wait for this k's bandwidth (published by the k-group's first CTA)
    spin_eq(&g_bwflag[k], 1);
    float inv = g_inv16[k];

    int ib = i0 + wm * 64 + (lane >> 2);
    int jb = j0 + wn * 32 + 2 * (lane & 3);
    float sqj[8];
    #pragma unroll
    for (int nf = 0; nf < 4; nf++) {
        sqj[nf * 2 + 0] = g_sq[k * M2 + jb + nf * 8 + 0];
        sqj[nf * 2 + 1] = g_sq[k * M2 + jb + nf * 8 + 1];
    }
    float av = 0.f;
    #pragma unroll
    for (int mf = 0; mf < 4; mf++) {
        #pragma unroll
        for (int rr = 0; rr < 2; rr++) {
            int i = ib + mf * 16 + rr * 8;
            float sqi = g_sq[k * M2 + i];
            bool hi = (i < BSZ);
            #pragma unroll
            for (int nf = 0; nf < 4; nf++) {
                #pragma unroll
                for (int e = 0; e < 2; e++) {
                    int j = jb + nf * 8 + e;
                    float d2 = sqi + sqj[nf * 2 + e] - 2.f * acc[mf][nf][rr * 2 + e];
                    float ex = __expf(-d2 * inv);
                    float s5 = ex;
                    ex *= ex; s5 += ex;
                    ex *= ex; s5 += ex;
                    ex *= ex; s5 += ex;
                    ex *= ex; s5 += ex;
                    float w = (j > i) ? 2.f : ((j == i) ? 1.f : 0.f);
                    float sg = (hi == (j < BSZ)) ? 1.f : -1.f;
                    av += sg * w * s5;
                }
            }
        }
    }
    #pragma unroll
    for (int o = 16; o; o >>= 1) av += __shfl_xor_sync(0xffffffffu, av, o);
    __syncthreads();
    if (lane == 0) red[wid] = av;
    __syncthreads();
    if (threadIdx.x == 0) {
        float s = 0.f;
        #pragma unroll
        for (int wq = 0; wq < 8; wq++) s += red[wq];
        atomicAdd(&g_mmd[k], (double)s);
        __threadfence();
        atomicAdd(&g_gdone, 1);
    }
}

// ================= clsdisc path (waits on all mm1, overlaps gram tail) =======
__device__ void clsdisc_work(int b, char* smem, const float* __restrict__ y,
        const float* __restrict__ W_cls, const float* __restrict__ b_cls, int subj) {
    spin_eq(&g_mm1all, KS * 64);

    float* P    = (float*)smem;          // [KS][513]
    float* tp   = P + KS * 513;          // [KS][3]
    float* clss = tp + KS * 3;           // [KS]
    float* ws   = clss + KS;             // [8]
    int w = threadIdx.x >> 5, lane = threadIdx.x & 31;

    for (int k = w; k < KS; k += 8) {
        const float* row = g_total + ((size_t)k * M2 + b) * DD;
        float v[16];
        #pragma unroll
        for (int i = 0; i < 16; i++) v[i] = row[lane + 32 * i];
        float m = v[0];
        #pragma unroll
        for (int i = 1; i < 16; i++) m = fmaxf(m, v[i]);
        #pragma unroll
        for (int o = 16; o; o >>= 1) m = fmaxf(m, __shfl_xor_sync(0xffffffffu, m, o));
        float e[16], ssum = 0.f;
        #pragma unroll
        for (int i = 0; i < 16; i++) { e[i] = __expf(v[i] - m); ssum += e[i]; }
        #pragma unroll
        for (int o = 16; o; o >>= 1) ssum += __shfl_xor_sync(0xffffffffu, ssum, o);
        float invs = 1.f / ssum;
        #pragma unroll
        for (int i = 0; i < 16; i++) P[k * 513 + lane + 32 * i] = e[i] * invs;

        const float* Wc = W_cls + (size_t)k * 3 * DD;
        float a0 = 0.f, a1 = 0.f, a2 = 0.f;
        #pragma unroll
        for (int i = 0; i < 16; i++) {
            float r = fmaxf(v[i], 0.f);
            int d = lane + 32 * i;
            a0 += r * Wc[d]; a1 += r * Wc[DD + d]; a2 += r * Wc[2 * DD + d];
        }
        #pragma unroll
        for (int o = 16; o; o >>= 1) {
            a0 += __shfl_xor_sync(0xffffffffu, a0, o);
            a1 += __shfl_xor_sync(0xffffffffu, a1, o);
            a2 += __shfl_xor_sync(0xffffffffu, a2, o);
        }
        if (lane == 0) {
            float l0 = a0 + b_cls[k * 3 + 0];
            float l1 = a1 + b_cls[k * 3 + 1];
            float l2 = a2 + b_cls[k * 3 + 2];
            float mm = fmaxf(l0, fmaxf(l1, l2));
            float s = __expf(l0 - mm) + __expf(l1 - mm) + __expf(l2 - mm);
            int sk = (k < subj) ? k : k + 1;
            const float* yr = y + (size_t)(sk * BSZ + b) * 3;
            int lab = (yr[1] > yr[0]) ? ((yr[2] > yr[1]) ? 2 : 1) : ((yr[2] > yr[0]) ? 2 : 0);
            float li = (lab == 0) ? l0 : ((lab == 1) ? l1 : l2);
            clss[k] = mm + logf(s) - li;
        }

        const float* trow = g_total + ((size_t)k * M2 + BSZ + b) * DD;
        #pragma unroll
        for (int i = 0; i < 16; i++) v[i] = trow[lane + 32 * i];
        a0 = a1 = a2 = 0.f;
        #pragma unroll
        for (int i = 0; i < 16; i++) {
            float r = fmaxf(v[i], 0.f);
            int d = lane + 32 * i;
            a0 += r * Wc[d]; a1 += r * Wc[DD + d]; a2 += r * Wc[2 * DD + d];
        }
        #pragma unroll
        for (int o = 16; o; o >>= 1) {
            a0 += __shfl_xor_sync(0xffffffffu, a0, o);
            a1 += __shfl_xor_sync(0xffffffffu, a1, o);
            a2 += __shfl_xor_sync(0xffffffffu, a2, o);
        }
        if (lane == 0) {
            float l0 = a0 + b_cls[k * 3 + 0];
            float l1 = a1 + b_cls[k * 3 + 1];
            float l2 = a2 + b_cls[k * 3 + 2];
            float mm = fmaxf(l0, fmaxf(l1, l2));
            float e0 = __expf(l0 - mm), e1 = __expf(l1 - mm), e2 = __expf(l2 - mm);
            float is = 1.f / (e0 + e1 + e2);
            tp[k * 3 + 0] = e0 * is; tp[k * 3 + 1] = e1 * is; tp[k * 3 + 2] = e2 * is;
        }
    }
    __syncthreads();

    float acc = 0.f;
    for (int d = threadIdx.x; d < DD; d += 256) {
        float p[KS];
        #pragma unroll
        for (int k = 0; k < KS; k++) p[k] = P[k * 513 + d];
        #pragma unroll
        for (int i = 0; i < KS; i++)
            #pragma unroll
            for (int j = i + 1; j < KS; j++)
                acc += fabsf(p[i] - p[j]);
    }
    #pragma unroll
    for (int o = 16; o; o >>= 1) acc += __shfl_xor_sync(0xffffffffu, acc, o);
    if (lane == 0) ws[w] = acc;
    __syncthreads();
    if (threadIdx.x == 0) {
        float s = 0.f;
        #pragma unroll
        for (int i = 0; i < 8; i++) s += ws[i];
        atomicAdd(&g_disc, (double)s);
        float cl = 0.f;
        #pragma unroll
        for (int k = 0; k < KS; k++) cl += clss[k];
        atomicAdd(&g_cls, (double)cl);
        float p0 = 0.f, p1 = 0.f, p2 = 0.f;
        #pragma unroll
        for (int k = 0; k < KS; k++) { p0 += tp[k * 3 + 0]; p1 += tp[k * 3 + 1]; p2 += tp[k * 3 + 2]; }
        int am = (p1 > p0) ? ((p2 > p1) ? 2 : 1) : ((p2 > p0) ? 2 : 0);
        const float* yt = y + (size_t)(subj * BSZ + b) * 3;
        int lab = (yt[1] > yt[0]) ? ((yt[2] > yt[1]) ? 2 : 1) : ((yt[2] > yt[0]) ? 2 : 0);
        if (am == lab) atomicAdd(&g_pred, 1);
        __threadfence();
        atomicAdd(&g_cdone, 1);
    }
}

// ================= finalize: emit outputs, then reset state for next replay ===
__device__ void fin_work(float* out) {
    if (threadIdx.x == 0) {
        while (ld_acq(&g_gdone) != GRAM_CTAS) __nanosleep(256);
        while (ld_acq(&g_cdone) != CLS_CTAS) __nanosleep(256);
        double mmd = 0.0;
        for (int k = 0; k < KS; k++) mmd += g_mmd[k];
        mmd /= (double)KS * (double)BSZ * (double)BSZ;
        out[0] = (float)(0.1 * mmd);
        double disc = g_disc / ((double)BSZ * (double)DD) * 2.0 / ((double)KS * (KS - 1));
        out[1] = (float)(0.4 * disc);
        out[2] = (float)(g_cls / ((double)KS * (double)BSZ));
        out[3] = (float)g_pred;
        out[4] = (float)BSZ;
        // reset scalars for next graph replay
        g_cls = 0.0; g_disc = 0.0; g_pred = 0;
        g_gdone = 0; g_cdone = 0; g_mm1all = 0;
    }
    __syncthreads();
    // reset accumulator arrays (statically zero on first run)
    for (int i = threadIdx.x; i < KS * M2; i += 256) g_sq[i] = 0.f;
    for (int i = threadIdx.x; i < KS * DD; i += 256) g_cs[i] = 0.f;
    if (threadIdx.x < KS) { g_mmd[threadIdx.x] = 0.0; g_done[threadIdx.x] = 0; g_bwflag[threadIdx.x] = 0; }
    if (threadIdx.x < SNUM) g_sdone[threadIdx.x] = 0;
}

// ---------------- single mega kernel, split/mm1 interleaved -------------------
__global__ __launch_bounds__(256, 2) void k_mega(
        const float* __restrict__ x, const float* __restrict__ y,
        const float* __restrict__ W_add, const float* __restrict__ b_add,
        const float* __restrict__ W_cls, const float* __restrict__ b_cls,
        const int* __restrict__ subj_p, float* __restrict__ out) {
    extern __shared__ char smem[];
    uint32_t sb = smem_u32(smem);
    int bid = blockIdx.x;
    int subj = *subj_p;
    if (bid < B_INTER) {
        // interleaved prologue: [split p0][split p1][mm1 k0][split p2][mm1 k1]...
        if (bid < 64) {
            split_item(0, bid, subj, x, W_add);
        } else {
            int r = bid - 64;
            int g = r >> 7;      // 0..13
            int q = r & 127;
            if (q < 64) split_item(g + 1, q, subj, x, W_add);
            else        mm1_work(sb, g, q - 64, b_add, subj);
        }
    }
    else if (bid < B_CLS)  gram_work(sb, bid - B_INTER, smem);
    else if (bid < B_FIN)  clsdisc_work(bid - B_CLS, smem, y, W_cls, b_cls, subj);
    else                   fin_work(out);
}

// ---------------- launch ----------------
extern "C" void kernel_launch(void* const* d_in, const int* in_sizes, int n_in,
                              void* d_out, int out_size) {
    const float* x     = (const float*)d_in[0];
    const float* y     = (const float*)d_in[1];
    const float* W_add = (const float*)d_in[3];
    const float* b_add = (const float*)d_in[4];
    const float* W_cls = (const float*)d_in[5];
    const float* b_cls = (const float*)d_in[6];
    const int*   subj  = (const int*)d_in[7];

    cudaFuncSetAttribute(k_mega, cudaFuncAttributeMaxDynamicSharedMemorySize, SMEM_FUSED);

    k_mega<<<TOT_CTAS, 256, SMEM_FUSED>>>(x, y, W_add, b_add, W_cls, b_cls, subj, (float*)d_out);
}

// round 16
// speedup vs baseline: 1.0223x; 1.0223x over previous
#include <cuda_runtime.h>
#include <cuda_bf16.h>
#include <math.h>
#include <stdint.h>

#define KS 14      // source subjects (S-1)
#define SNUM 15
#define BSZ 1024
#define CD 2048
#define DD 512
#define M2 2048

#define STAGE_B 32768u      // mm1 stage bytes
#define SMEM_FUSED (3 * 32768)
#define GSTAGE_B 16384u     // gram stage bytes

#define SPLIT_SLICES 64
// interleaved prologue: [split p0][split p1][mm1 k0][split p2][mm1 k1]...
#define B_INTER (64 + 14 * 128)             // 1856 = 960 split + 896 mm1
#define GRAM_PER_K 136                      // 16*17/2 upper-triangle tiles
#define GRAM_CTAS (KS * GRAM_PER_K)         // 1904
#define CLS_CTAS BSZ                        // 1024
#define B_CLS   (B_INTER + GRAM_CTAS)       // 3760
#define B_FIN   (B_CLS + CLS_CTAS)          // 4784
#define TOT_CTAS (B_FIN + 1)                // 4785

// ---------------- scratch (static zero-init; fin resets per run) -------------
__device__ __nv_bfloat16 g_x1[(size_t)SNUM * BSZ * CD];
__device__ __nv_bfloat16 g_x2[(size_t)SNUM * BSZ * CD];
__device__ __nv_bfloat16 g_w1[(size_t)SNUM * DD * CD];
__device__ __nv_bfloat16 g_w2[(size_t)SNUM * DD * CD];
__device__ __nv_bfloat16 g_t1[(size_t)KS * M2 * DD];
__device__ float  g_total[(size_t)KS * M2 * DD];
__device__ float  g_sq[KS * M2];
__device__ float  g_cs[KS * DD];
__device__ float  g_inv16[KS];
__device__ int    g_bwflag[KS];
__device__ int    g_sdone[SNUM];
__device__ int    g_done[KS];
__device__ int    g_mm1all;
__device__ int    g_gdone;
__device__ int    g_cdone;
__device__ double g_mmd[KS];
__device__ double g_cls;
__device__ double g_disc;
__device__ int    g_pred;

// ---------------- helpers (compute_80-level PTX only) ----------------
__device__ __forceinline__ uint32_t smem_u32(const void* p) {
    uint32_t a;
    asm("{ .reg .u64 t; cvta.to.shared.u64 t, %1; cvt.u32.u64 %0, t; }" : "=r"(a) : "l"(p));
    return a;
}
__device__ __forceinline__ void cpa(uint32_t dst, const void* src) {
    asm volatile("cp.async.cg.shared.global [%0], [%1], 16;" :: "r"(dst), "l"(src) : "memory");
}
__device__ __forceinline__ void ldsm4(uint32_t* r, uint32_t a) {
    asm volatile("ldmatrix.sync.aligned.m8n8.x4.shared.b16 {%0,%1,%2,%3}, [%4];"
                 : "=r"(r[0]), "=r"(r[1]), "=r"(r[2]), "=r"(r[3]) : "r"(a));
}
__device__ __forceinline__ void mma16816(float* c, const uint32_t* a, const uint32_t* b) {
    asm volatile("mma.sync.aligned.m16n8k16.row.col.f32.bf16.bf16.f32 "
                 "{%0,%1,%2,%3}, {%4,%5,%6,%7}, {%8,%9}, {%0,%1,%2,%3};"
                 : "+f"(c[0]), "+f"(c[1]), "+f"(c[2]), "+f"(c[3])
                 : "r"(a[0]), "r"(a[1]), "r"(a[2]), "r"(a[3]), "r"(b[0]), "r"(b[1]));
}
__device__ __forceinline__ int ld_acq(const int* p) {
    int v;
    asm volatile("ld.acquire.gpu.b32 %0, [%1];" : "=r"(v) : "l"(p) : "memory");
    return v;
}
__device__ __forceinline__ void spin_eq(const int* p, int want) {
    if (threadIdx.x == 0) {
        while (ld_acq(p) != want) __nanosleep(64);
    }
    __syncthreads();
}

// ================= split item: 1/64 of one subject's x+W bf16 hi/lo ==========
__device__ void split_item(int p, int slice, int subj, const float* __restrict__ x,
                           const float* __restrict__ W) {
    int s = (p == 0) ? subj : (((p - 1) < subj) ? (p - 1) : p);
    const int XC = BSZ * CD / 4 / SPLIT_SLICES;   // 8192 float4
    const int WC = DD * CD / 4 / SPLIT_SLICES;    // 4096 float4
    size_t xo = (size_t)s * (BSZ * CD / 4) + (size_t)slice * XC;
    #pragma unroll 8
    for (int i = 0; i < XC / 256; i++) {
        size_t u = xo + i * 256 + threadIdx.x;
        float4 v = ((const float4*)x)[u];
        __nv_bfloat162 h0, h1, l0, l1;
        h0.x = __float2bfloat16(v.x); h0.y = __float2bfloat16(v.y);
        h1.x = __float2bfloat16(v.z); h1.y = __float2bfloat16(v.w);
        l0.x = __float2bfloat16(v.x - __bfloat162float(h0.x));
        l0.y = __float2bfloat16(v.y - __bfloat162float(h0.y));
        l1.x = __float2bfloat16(v.z - __bfloat162float(h1.x));
        l1.y = __float2bfloat16(v.w - __bfloat162float(h1.y));
        ((__nv_bfloat162*)g_x1)[2 * u] = h0; ((__nv_bfloat162*)g_x1)[2 * u + 1] = h1;
        ((__nv_bfloat162*)g_x2)[2 * u] = l0; ((__nv_bfloat162*)g_x2)[2 * u + 1] = l1;
    }
    size_t wo = (size_t)s * (DD * CD / 4) + (size_t)slice * WC;
    #pragma unroll 8
    for (int i = 0; i < WC / 256; i++) {
        size_t u = wo + i * 256 + threadIdx.x;
        float4 v = ((const float4*)W)[u];
        __nv_bfloat162 h0, h1, l0, l1;
        h0.x = __float2bfloat16(v.x); h0.y = __float2bfloat16(v.y);
        h1.x = __float2bfloat16(v.z); h1.y = __float2bfloat16(v.w);
        l0.x = __float2bfloat16(v.x - __bfloat162float(h0.x));
        l0.y = __float2bfloat16(v.y - __bfloat162float(h0.y));
        l1.x = __float2bfloat16(v.z - __bfloat162float(h1.x));
        l1.y = __float2bfloat16(v.w - __bfloat162float(h1.y));
        ((__nv_bfloat162*)g_w1)[2 * u] = h0; ((__nv_bfloat162*)g_w1)[2 * u + 1] = h1;
        ((__nv_bfloat162*)g_w2)[2 * u] = l0; ((__nv_bfloat162*)g_w2)[2 * u + 1] = l1;
    }
    __threadfence();
    __syncthreads();
    if (threadIdx.x == 0) atomicAdd(&g_sdone[s], 1);
}

// ================= mm1 path: 8 warps, warp tile 64x32, 3-product ============
__device__ __forceinline__ void ld_stage(uint32_t sb, int stg,
        const __nv_bfloat16* A1, const __nv_bfloat16* A2,
        const __nv_bfloat16* B1, const __nv_bfloat16* B2, int kt) {
    int tid = threadIdx.x;
    int half = tid & 1, row = tid >> 1;
    uint32_t s0 = sb + (uint32_t)stg * STAGE_B;
    uint32_t roff = (uint32_t)(row * 32) + (uint32_t)((half ^ ((row >> 2) & 1)) * 16);
    const __nv_bfloat16* ptrs[4] = {A1, A2, B1, B2};
    #pragma unroll
    for (int it = 0; it < 8; it++) {
        const int arr = it >> 1, kc = it & 1;
        cpa(s0 + (uint32_t)(arr * 8192 + kc * 4096) + roff,
            ptrs[arr] + (size_t)row * CD + kt + kc * 16 + half * 8);
    }
    asm volatile("cp.async.commit_group;" ::: "memory");
}

__device__ __forceinline__ void cmp_stage(uint32_t s0, int wm, int wn, int lane,
                                          float (*acc)[4][4]) {
    int arow = wm * 64 + (lane & 15);
    int ah = lane >> 4;
    int brow = wn * 32 + (lane & 7) + ((lane >> 4) << 3);
    int bh = (lane >> 3) & 1;
    #pragma unroll
    for (int kk = 0; kk < 2; kk++) {
        uint32_t base = s0 + (uint32_t)(kk * 4096);
        uint32_t af1[4][4], af2[4][4], bfr1[2][4], bfr2[2][4];
        #pragma unroll
        for (int mf = 0; mf < 4; mf++) {
            int r = arow + mf * 16;
            uint32_t off = (uint32_t)(r * 32 + ((ah ^ ((r >> 2) & 1)) * 16));
            ldsm4(af1[mf], base + off);
            ldsm4(af2[mf], base + 8192 + off);
        }
        #pragma unroll
        for (int np = 0; np < 2; np++) {
            int r = brow + np * 16;
            uint32_t off = (uint32_t)(r * 32 + ((bh ^ ((r >> 2) & 1)) * 16));
            ldsm4(bfr1[np], base + 16384 + off);
            ldsm4(bfr2[np], base + 24576 + off);
        }
        #pragma unroll
        for (int mf = 0; mf < 4; mf++)
            #pragma unroll
            for (int nf = 0; nf < 4; nf++) {
                const uint32_t* b1 = &bfr1[nf >> 1][(nf & 1) * 2];
                const uint32_t* b2 = &bfr2[nf >> 1][(nf & 1) * 2];
                mma16816(acc[mf][nf], af1[mf], b1);
                mma16816(acc[mf][nf], af1[mf], b2);
                mma16816(acc[mf][nf], af2[mf], b1);
            }
    }
}

__device__ void mm1_work(uint32_t sb, int k, int t,
                         const float* __restrict__ b_add, int subj) {
    int n0 = (t & 3) * 128;
    int i0 = (t >> 2) * 128;
    int sk = (k < subj) ? k : k + 1;

    // wait for bf16 splits of the two subjects this tile reads
    if (threadIdx.x == 0) {
        while (ld_acq(&g_sdone[sk]) != SPLIT_SLICES) __nanosleep(64);
        while (ld_acq(&g_sdone[subj]) != SPLIT_SLICES) __nanosleep(64);
    }
    __syncthreads();

    int arow0 = (i0 < BSZ) ? (sk * BSZ + i0) : (subj * BSZ + (i0 - BSZ));
    const __nv_bfloat16* A1 = g_x1 + (size_t)arow0 * CD;
    const __nv_bfloat16* A2 = g_x2 + (size_t)arow0 * CD;
    const __nv_bfloat16* B1 = g_w1 + ((size_t)sk * DD + n0) * CD;
    const __nv_bfloat16* B2 = g_w2 + ((size_t)sk * DD + n0) * CD;

    float acc[4][4][4];
    #pragma unroll
    for (int a = 0; a < 4; a++)
        #pragma unroll
        for (int b = 0; b < 4; b++)
            #pragma unroll
            for (int c = 0; c < 4; c++) acc[a][b][c] = 0.f;

    int tid = threadIdx.x, lane = tid & 31, wid = tid >> 5;
    int wm = wid & 1, wn = wid >> 1;
    ld_stage(sb, 0, A1, A2, B1, B2, 0);
    ld_stage(sb, 1, A1, A2, B1, B2, 32);
    const int NT = CD / 32;
    for (int ic = 0; ic < NT; ic++) {
        asm volatile("cp.async.wait_group 1;" ::: "memory");
        __syncthreads();
        if (ic + 2 < NT)
            ld_stage(sb, (ic + 2) % 3, A1, A2, B1, B2, (ic + 2) * 32);
        else
            asm volatile("cp.async.commit_group;" ::: "memory");
        cmp_stage(sb + (uint32_t)(ic % 3) * STAGE_B, wm, wn, lane, acc);
    }
    __syncthreads();

    // epilogue: bias, store fp32 + bf16(hi), row sq-norms, fused column sums
    int rb = i0 + wm * 64 + (lane >> 2);
    int cb = n0 + wn * 32 + 2 * (lane & 3);
    float csum[8];
    #pragma unroll
    for (int q = 0; q < 8; q++) csum[q] = 0.f;
    #pragma unroll
    for (int mf = 0; mf < 4; mf++) {
        #pragma unroll
        for (int rr = 0; rr < 2; rr++) {
            int row = rb + mf * 16 + rr * 8;
            float* trow = g_total + ((size_t)k * M2 + row) * DD;
            __nv_bfloat16* t1r = g_t1 + ((size_t)k * M2 + row) * DD;
            float s = 0.f;
            #pragma unroll
            for (int nf = 0; nf < 4; nf++) {
                int col = cb + nf * 8;
                float v0 = acc[mf][nf][rr * 2 + 0] + b_add[sk * DD + col];
                float v1 = acc[mf][nf][rr * 2 + 1] + b_add[sk * DD + col + 1];
                *(float2*)(trow + col) = make_float2(v0, v1);
                __nv_bfloat162 ph;
                ph.x = __float2bfloat16(v0);
                ph.y = __float2bfloat16(v1);
                *(__nv_bfloat162*)(t1r + col) = ph;
                s += v0 * v0 + v1 * v1;
                csum[nf * 2 + 0] += v0;
                csum[nf * 2 + 1] += v1;
            }
            s += __shfl_xor_sync(0xffffffffu, s, 1);
            s += __shfl_xor_sync(0xffffffffu, s, 2);
            if ((lane & 3) == 0) atomicAdd(&g_sq[k * M2 + row], s);
        }
    }
    #pragma unroll
    for (int q = 0; q < 8; q++) {
        csum[q] += __shfl_xor_sync(0xffffffffu, csum[q], 4);
        csum[q] += __shfl_xor_sync(0xffffffffu, csum[q], 8);
        csum[q] += __shfl_xor_sync(0xffffffffu, csum[q], 16);
    }
    if ((lane >> 2) == 0) {
        #pragma unroll
        for (int nf = 0; nf < 4; nf++) {
            atomicAdd(&g_cs[k * DD + cb + nf * 8 + 0], csum[nf * 2 + 0]);
            atomicAdd(&g_cs[k * DD + cb + nf * 8 + 1], csum[nf * 2 + 1]);
        }
    }
    __threadfence();
    __syncthreads();
    if (threadIdx.x == 0) {
        atomicAdd(&g_done[k], 1);
        atomicAdd(&g_mm1all, 1);
    }
}

// ================= gram path: 1-product bf16, 8 warps, 64x32 warp tile ========
__device__ __forceinline__ void ld_stage_g(uint32_t sb, int stg,
        const __nv_bfloat16* A, const __nv_bfloat16* B, int kt) {
    int tid = threadIdx.x;
    int half = tid & 1, row = tid >> 1;
    uint32_t s0 = sb + (uint32_t)stg * GSTAGE_B;
    uint32_t roff = (uint32_t)(row * 32) + (uint32_t)((half ^ ((row >> 2) & 1)) * 16);
    const __nv_bfloat16* ptrs[2] = {A, B};
    #pragma unroll
    for (int it = 0; it < 4; it++) {
        const int arr = it >> 1, kc = it & 1;
        cpa(s0 + (uint32_t)(arr * 8192 + kc * 4096) + roff,
            ptrs[arr] + (size_t)row * DD + kt + kc * 16 + half * 8);
    }
    asm volatile("cp.async.commit_group;" ::: "memory");
}

__device__ __forceinline__ void cmp_stage_g(uint32_t s0, int wm, int wn, int lane,
                                            float (*acc)[4][4]) {
    int arow = wm * 64 + (lane & 15);
    int ah = lane >> 4;
    int brow = wn * 32 + (lane & 7) + ((lane >> 4) << 3);
    int bh = (lane >> 3) & 1;
    #pragma unroll
    for (int kk = 0; kk < 2; kk++) {
        uint32_t base = s0 + (uint32_t)(kk * 4096);
        uint32_t af[4][4], bfr[2][4];
        #pragma unroll
        for (int mf = 0; mf < 4; mf++) {
            int r = arow + mf * 16;
            uint32_t off = (uint32_t)(r * 32 + ((ah ^ ((r >> 2) & 1)) * 16));
            ldsm4(af[mf], base + off);
        }
        #pragma unroll
        for (int np = 0; np < 2; np++) {
            int r = brow + np * 16;
            uint32_t off = (uint32_t)(r * 32 + ((bh ^ ((r >> 2) & 1)) * 16));
            ldsm4(bfr[np], base + 8192 + off);
        }
        #pragma unroll
        for (int mf = 0; mf < 4; mf++)
            #pragma unroll
            for (int nf = 0; nf < 4; nf++)
                mma16816(acc[mf][nf], af[mf], &bfr[nf >> 1][(nf & 1) * 2]);
    }
}

__device__ void gram_work(uint32_t sb, int gid, char* smem) {
    int k = gid / GRAM_PER_K;
    int t = gid % GRAM_PER_K;
    int bi = 0;
    while (t >= 16 - bi) { t -= 16 - bi; bi++; }
    int bj = bi + t;
    bool bw_owner = (gid % GRAM_PER_K) == 0;

    spin_eq(&g_done[k], 64);

    int tid = threadIdx.x, lane = tid & 31, wid = tid >> 5;
    float* red = (float*)smem;

    // first gram CTA of this k computes 1/(16*bandwidth) for everyone
    if (bw_owner) {
        float s2 = 0.f;
        for (int d = tid; d < DD; d += 256) { float c = g_cs[k * DD + d]; s2 += c * c; }
        float qq = 0.f;
        for (int i = tid; i < M2; i += 256) qq += g_sq[k * M2 + i];
        #pragma unroll
        for (int o = 16; o; o >>= 1) {
            s2 += __shfl_xor_sync(0xffffffffu, s2, o);
            qq += __shfl_xor_sync(0xffffffffu, qq, o);
        }
        if (lane == 0) { red[wid] = s2; red[8 + wid] = qq; }
        __syncthreads();
        if (tid == 0) {
            float ssum = 0.f, sqsum = 0.f;
            #pragma unroll
            for (int i = 0; i < 8; i++) { ssum += red[i]; sqsum += red[8 + i]; }
            double m = (double)M2;
            double sumd2 = 2.0 * m * (double)sqsum - 2.0 * (double)ssum;
            double bw = sumd2 / (m * m - m) / 4.0;
            g_inv16[k] = (float)(1.0 / (16.0 * bw));
            __threadfence();
            atomicExch(&g_bwflag[k], 1);
        }
        __syncthreads();
    }

    int i0 = bi * 128, j0 = bj * 128;
    const __nv_bfloat16* A = g_t1 + ((size_t)k * M2 + i0) * DD;
    const __nv_bfloat16* B = g_t1 + ((size_t)k * M2 + j0) * DD;

    float acc[4][4][4];
    #pragma unroll
    for (int a = 0; a < 4; a++)
        #pragma unroll
        for (int b = 0; b < 4; b++)
            #pragma unroll
            for (int c = 0; c < 4; c++) acc[a][b][c] = 0.f;

    int wm = wid & 1, wn = wid >> 1;
    ld_stage_g(sb, 0, A, B, 0);
    ld_stage_g(sb, 1, A, B, 32);
    const int NT = DD / 32;
    for (int ic = 0; ic < NT; ic++) {
        asm volatile("cp.async.wait_group 1;" ::: "memory");
        __syncthreads();
        if (ic + 2 < NT)
            ld_stage_g(sb, (ic + 2) % 3, A, B, (ic + 2) * 32);
        else
            asm volatile("cp.async.commit_group;" ::: "memory");
        cmp_stage_g(sb + (uint32_t)(ic % 3) * GSTAGE_B, wm, wn, lane, acc);
    }
    __syncthreads();

    // wait for this k's bandwidth (published by the k-group's first CTA)
    spin_eq(&g_bwflag[k], 1);
    float inv = g_inv16[k];

    int ib = i0 + wm * 64 + (lane >> 2);
    int jb = j0 + wn * 32 + 2 * (lane & 3);
    float sqj[8];
    #pragma unroll
    for (int nf = 0; nf < 4; nf++) {
        sqj[nf * 2 + 0] = g_sq[k * M2 + jb + nf * 8 + 0];
        sqj[nf * 2 + 1] = g_sq[k * M2 + jb + nf * 8 + 1];
    }
    float av = 0.f;
    #pragma unroll
    for (int mf = 0; mf < 4; mf++) {
        #pragma unroll
        for (int rr = 0; rr < 2; rr++) {
            int i = ib + mf * 16 + rr * 8;
            float sqi = g_sq[k * M2 + i];
            bool hi = (i < BSZ);
            #pragma unroll
            for (int nf = 0; nf < 4; nf++) {
                #pragma unroll
                for (int e = 0; e < 2; e++) {
                    int j = jb + nf * 8 + e;
                    float d2 = sqi + sqj[nf * 2 + e] - 2.f * acc[mf][nf][rr * 2 + e];
                    float ex = __expf(-d2 * inv);
                    float s5 = ex;
                    ex *= ex; s5 += ex;
                    ex *= ex; s5 += ex;
                    ex *= ex; s5 += ex;
                    ex *= ex; s5 += ex;
                    float w = (j > i) ? 2.f : ((j == i) ? 1.f : 0.f);
                    float sg = (hi == (j < BSZ)) ? 1.f : -1.f;
                    av += sg * w * s5;
                }
            }
        }
    }
    #pragma unroll
    for (int o = 16; o; o >>= 1) av += __shfl_xor_sync(0xffffffffu, av, o);
    __syncthreads();
    if (lane == 0) red[wid] = av;
    __syncthreads();
    if (threadIdx.x == 0) {
        float s = 0.f;
        #pragma unroll
        for (int wq = 0; wq < 8; wq++) s += red[wq];
        atomicAdd(&g_mmd[k], (double)s);
        __threadfence();
        atomicAdd(&g_gdone, 1);
    }
}

// ================= clsdisc path (waits on all mm1, overlaps gram tail) =======
__device__ void clsdisc_work(int b, char* smem, const float* __restrict__ y,
        const float* __restrict__ W_cls, const float* __restrict__ b_cls, int subj) {
    spin_eq(&g_mm1all, KS * 64);

    float* P    = (float*)smem;          // [KS][513]
    float* tp   = P + KS * 513;          // [KS][3]
    float* clss = tp + KS * 3;           // [KS]
    float* ws   = clss + KS;             // [8]
    int w = threadIdx.x >> 5, lane = threadIdx.x & 31;

    for (int k = w; k < KS; k += 8) {
        const float* row = g_total + ((size_t)k * M2 + b) * DD;
        float v[16];
        #pragma unroll
        for (int i = 0; i < 16; i++) v[i] = row[lane + 32 * i];
        float m = v[0];
        #pragma unroll
        for (int i = 1; i < 16; i++) m = fmaxf(m, v[i]);
        #pragma unroll
        for (int o = 16; o; o >>= 1) m = fmaxf(m, __shfl_xor_sync(0xffffffffu, m, o));
        float e[16], ssum = 0.f;
        #pragma unroll
        for (int i = 0; i < 16; i++) { e[i] = __expf(v[i] - m); ssum += e[i]; }
        #pragma unroll
        for (int o = 16; o; o >>= 1) ssum += __shfl_xor_sync(0xffffffffu, ssum, o);
        float invs = 1.f / ssum;
        #pragma unroll
        for (int i = 0; i < 16; i++) P[k * 513 + lane + 32 * i] = e[i] * invs;

        const float* Wc = W_cls + (size_t)k * 3 * DD;
        float a0 = 0.f, a1 = 0.f, a2 = 0.f;
        #pragma unroll
        for (int i = 0; i < 16; i++) {
            float r = fmaxf(v[i], 0.f);
            int d = lane + 32 * i;
            a0 += r * Wc[d]; a1 += r * Wc[DD + d]; a2 += r * Wc[2 * DD + d];
        }
        #pragma unroll
        for (int o = 16; o; o >>= 1) {
            a0 += __shfl_xor_sync(0xffffffffu, a0, o);
            a1 += __shfl_xor_sync(0xffffffffu, a1, o);
            a2 += __shfl_xor_sync(0xffffffffu, a2, o);
        }
        if (lane == 0) {
            float l0 = a0 + b_cls[k * 3 + 0];
            float l1 = a1 + b_cls[k * 3 + 1];
            float l2 = a2 + b_cls[k * 3 + 2];
            float mm = fmaxf(l0, fmaxf(l1, l2));
            float s = __expf(l0 - mm) + __expf(l1 - mm) + __expf(l2 - mm);
            int sk = (k < subj) ? k : k + 1;
            const float* yr = y + (size_t)(sk * BSZ + b) * 3;
            int lab = (yr[1] > yr[0]) ? ((yr[2] > yr[1]) ? 2 : 1) : ((yr[2] > yr[0]) ? 2 : 0);
            float li = (lab == 0) ? l0 : ((lab == 1) ? l1 : l2);
            clss[k] = mm + logf(s) - li;
        }

        const float* trow = g_total + ((size_t)k * M2 + BSZ + b) * DD;
        #pragma unroll
        for (int i = 0; i < 16; i++) v[i] = trow[lane + 32 * i];
        a0 = a1 = a2 = 0.f;
        #pragma unroll
        for (int i = 0; i < 16; i++) {
            float r = fmaxf(v[i], 0.f);
            int d = lane + 32 * i;
            a0 += r * Wc[d]; a1 += r * Wc[DD + d]; a2 += r * Wc[2 * DD + d];
        }
        #pragma unroll
        for (int o = 16; o; o >>= 1) {
            a0 += __shfl_xor_sync(0xffffffffu, a0, o);
            a1 += __shfl_xor_sync(0xffffffffu, a1, o);
            a2 += __shfl_xor_sync(0xffffffffu, a2, o);
        }
        if (lane == 0) {
            float l0 = a0 + b_cls[k * 3 + 0];
            float l1 = a1 + b_cls[k * 3 + 1];
            float l2 = a2 + b_cls[k * 3 + 2];
            float mm = fmaxf(l0, fmaxf(l1, l2));
            float e0 = __expf(l0 - mm), e1 = __expf(l1 - mm), e2 = __expf(l2 - mm);
            float is = 1.f / (e0 + e1 + e2);
            tp[k * 3 + 0] = e0 * is; tp[k * 3 + 1] = e1 * is; tp[k * 3 + 2] = e2 * is;
        }
    }
    __syncthreads();

    float acc = 0.f;
    for (int d = threadIdx.x; d < DD; d += 256) {
        float p[KS];
        #pragma unroll
        for (int k = 0; k < KS; k++) p[k] = P[k * 513 + d];
        #pragma unroll
        for (int i = 0; i < KS; i++)
            #pragma unroll
            for (int j = i + 1; j < KS; j++)
                acc += fabsf(p[i] - p[j]);
    }
    #pragma unroll
    for (int o = 16; o; o >>= 1) acc += __shfl_xor_sync(0xffffffffu, acc, o);
    if (lane == 0) ws[w] = acc;
    __syncthreads();
    if (threadIdx.x == 0) {
        float s = 0.f;
        #pragma unroll
        for (int i = 0; i < 8; i++) s += ws[i];
        atomicAdd(&g_disc, (double)s);
        float cl = 0.f;
        #pragma unroll
        for (int k = 0; k < KS; k++) cl += clss[k];
        atomicAdd(&g_cls, (double)cl);
        float p0 = 0.f, p1 = 0.f, p2 = 0.f;
        #pragma unroll
        for (int k = 0; k < KS; k++) { p0 += tp[k * 3 + 0]; p1 += tp[k * 3 + 1]; p2 += tp[k * 3 + 2]; }
        int am = (p1 > p0) ? ((p2 > p1) ? 2 : 1) : ((p2 > p0) ? 2 : 0);
        const float* yt = y + (size_t)(subj * BSZ + b) * 3;
        int lab = (yt[1] > yt[0]) ? ((yt[2] > yt[1]) ? 2 : 1) : ((yt[2] > yt[0]) ? 2 : 0);
        if (am == lab) atomicAdd(&g_pred, 1);
        __threadfence();
        atomicAdd(&g_cdone, 1);
    }
}

// ================= finalize: emit outputs, then reset state for next replay ===
__device__ void fin_work(float* out) {
    if (threadIdx.x == 0) {
        while (ld_acq(&g_gdone) != GRAM_CTAS) __nanosleep(256);
        while (ld_acq(&g_cdone) != CLS_CTAS) __nanosleep(256);
        double mmd = 0.0;
        for (int k = 0; k < KS; k++) mmd += g_mmd[k];
        mmd /= (double)KS * (double)BSZ * (double)BSZ;
        out[0] = (float)(0.1 * mmd);
        double disc = g_disc / ((double)BSZ * (double)DD) * 2.0 / ((double)KS * (KS - 1));
        out[1] = (float)(0.4 * disc);
        out[2] = (float)(g_cls / ((double)KS * (double)BSZ));
        out[3] = (float)g_pred;
        out[4] = (float)BSZ;
        // reset scalars for next graph replay
        g_cls = 0.0; g_disc = 0.0; g_pred = 0;
        g_gdone = 0; g_cdone = 0; g_mm1all = 0;
    }
    __syncthreads();
    // reset accumulator arrays (statically zero on first run)
    for (int i = threadIdx.x; i < KS * M2; i += 256) g_sq[i] = 0.f;
    for (int i = threadIdx.x; i < KS * DD; i += 256) g_cs[i] = 0.f;
    if (threadIdx.x < KS) { g_mmd[threadIdx.x] = 0.0; g_done[threadIdx.x] = 0; g_bwflag[threadIdx.x] = 0; }
    if (threadIdx.x < SNUM) g_sdone[threadIdx.x] = 0;
}

// ---------------- single mega kernel, split/mm1 interleaved -------------------
__global__ __launch_bounds__(256, 2) void k_mega(
        const float* __restrict__ x, const float* __restrict__ y,
        const float* __restrict__ W_add, const float* __restrict__ b_add,
        const float* __restrict__ W_cls, const float* __restrict__ b_cls,
        const int* __restrict__ subj_p, float* __restrict__ out) {
    extern __shared__ char smem[];
    uint32_t sb = smem_u32(smem);
    int bid = blockIdx.x;
    int subj = *subj_p;
    if (bid < B_INTER) {
        // interleaved prologue: [split p0][split p1][mm1 k0][split p2][mm1 k1]...
        if (bid < 64) {
            split_item(0, bid, subj, x, W_add);
        } else {
            int r = bid - 64;
            int g = r >> 7;      // 0..13
            int q = r & 127;
            if (q < 64) split_item(g + 1, q, subj, x, W_add);
            else        mm1_work(sb, g, q - 64, b_add, subj);
        }
    }
    else if (bid < B_CLS)  gram_work(sb, bid - B_INTER, smem);
    else if (bid < B_FIN)  clsdisc_work(bid - B_CLS, smem, y, W_cls, b_cls, subj);
    else                   fin_work(out);
}

// ---------------- launch ----------------
extern "C" void kernel_launch(void* const* d_in, const int* in_sizes, int n_in,
                              void* d_out, int out_size) {
    const float* x     = (const float*)d_in[0];
    const float* y     = (const float*)d_in[1];
    const float* W_add = (const float*)d_in[3];
    const float* b_add = (const float*)d_in[4];
    const float* W_cls = (const float*)d_in[5];
    const float* b_cls = (const float*)d_in[6];
    const int*   subj  = (const int*)d_in[7];

    cudaFuncSetAttribute(k_mega, cudaFuncAttributeMaxDynamicSharedMemorySize, SMEM_FUSED);

    k_mega<<<TOT_CTAS, 256, SMEM_FUSED>>>(x, y, W_add, b_add, W_cls, b_cls, subj, (float*)d_out);
}